// round 8
// baseline (speedup 1.0000x reference)
#include <cuda_runtime.h>
#include <math.h>

#define T    2048
#define F    1024
#define NB   64          // total batch
#define HB   32          // half batch
#define KSEL 20
#define BPB  256         // blocks per batch
#define GRID (NB * BPB)              // 16384
#define NGATHER (NB * KSEL)          // 1280
#define GATHER_BASE (GRID - NGATHER) // gather duty on last-wave blocks

// scratch (no allocs allowed) — zero-init; reset at end of every launch
__device__ float g_mags[NB * T];
__device__ int   g_idx[NB * KSEL];
__device__ int   g_cnt[NB];
__device__ int   g_flag[NB];
__device__ int   g_done;

__device__ __forceinline__ int atom_add_acqrel(int* p, int v) {
    int old;
    asm volatile("atom.acq_rel.gpu.global.add.s32 %0, [%1], %2;"
                 : "=r"(old) : "l"(p), "r"(v) : "memory");
    return old;
}
__device__ __forceinline__ void st_release(int* p, int v) {
    asm volatile("st.release.gpu.global.b32 [%0], %1;" :: "l"(p), "r"(v) : "memory");
}
__device__ __forceinline__ int ld_acquire(const int* p) {
    int v;
    asm volatile("ld.acquire.gpu.global.b32 %0, [%1];" : "=r"(v) : "l"(p) : "memory");
    return v;
}

__global__ void __launch_bounds__(256)
fused_kernel(const float* __restrict__ feat,
             const float* __restrict__ scores,
             const float* __restrict__ mask_abn,
             const float* __restrict__ mask_nor,
             float* __restrict__ out) {
    int blk   = blockIdx.x;
    int batch = blk >> 8;
    int slice = blk & 255;
    int tid   = threadIdx.x;
    int lane  = tid & 31;
    int wid   = tid >> 5;

    // ---------------- phase 1: L2 norms for 8 rows (one warp per row) ------
    {
        int t = slice * 8 + wid;
        const float4* row = (const float4*)(feat + ((size_t)batch * T + t) * F);
        float s = 0.f;
#pragma unroll
        for (int i = 0; i < 8; i++) {
            float4 v = row[lane + i * 32];
            s += v.x * v.x + v.y * v.y + v.z * v.z + v.w * v.w;
        }
#pragma unroll
        for (int o = 16; o; o >>= 1) s += __shfl_xor_sync(0xffffffffu, s, o);
        if (lane == 0) g_mags[batch * T + t] = sqrtf(s);
    }
    __syncthreads();

    // last-arriver election: acq_rel atomic (NO __threadfence / L1 flush)
    __shared__ int s_last;
    if (tid == 0) s_last = (atom_add_acqrel(&g_cnt[batch], 1) == BPB - 1);
    __syncthreads();

    // ---------------- phase 2: top-K (warp-local top-20 + 8-way merge) -----
    if (s_last) {
        __shared__ float s_wv[8][21];
        __shared__ int   s_wi[8][21];

        int r = (batch >= HB) ? (batch - HB) : (batch + HB);  // output row
        const float* mask = (batch >= HB) ? mask_abn + (size_t)(batch - HB) * T
                                          : mask_nor + (size_t)batch * T;
        const float inv = 1.0f / 0.9f;   // 1/(1-P)
        float v[8];
#pragma unroll
        for (int j = 0; j < 8; j++) {
            int t = wid * 256 + j * 32 + lane;   // warp owns contiguous 256
            float d = (mask[t] > 0.1f) ? inv : 0.0f;
            v[j] = __ldcg(&g_mags[batch * T + t]) * d;
        }

        // 20 warp-local rounds, zero block syncs
        for (int k = 0; k < KSEL; k++) {
            float bv = -1.0f; int bi = 1 << 30;
#pragma unroll
            for (int j = 0; j < 8; j++) {
                if (v[j] > bv) { bv = v[j]; bi = wid * 256 + j * 32 + lane; }
            }
#pragma unroll
            for (int o = 16; o; o >>= 1) {
                float ov = __shfl_xor_sync(0xffffffffu, bv, o);
                int   oi = __shfl_xor_sync(0xffffffffu, bi, o);
                if (ov > bv || (ov == bv && oi < bi)) { bv = ov; bi = oi; }
            }
            if (lane == 0) { s_wv[wid][k] = bv; s_wi[wid][k] = bi; }
            int local = bi - wid * 256;                  // remove winner
            if ((local & 31) == lane) v[local >> 5] = -1.0f;
        }
        if (lane == 0) { s_wv[wid][20] = -2.0f; s_wi[wid][20] = 1 << 30; }
        __syncthreads();

        // warp 0: merge 8 descending lists of 20 (lane w<8 holds list head)
        if (wid == 0) {
            int   p  = 0;
            float hv = (lane < 8) ? s_wv[lane][0] : -3.0f;
            int   hi = (lane < 8) ? s_wi[lane][0] : (1 << 30);
            int my_idx = 0;
            for (int k = 0; k < KSEL; k++) {
                float fv = hv; int fi = hi;
#pragma unroll
                for (int o = 4; o; o >>= 1) {
                    float ov = __shfl_xor_sync(0xffffffffu, fv, o);
                    int   oi = __shfl_xor_sync(0xffffffffu, fi, o);
                    if (ov > fv || (ov == fv && oi < fi)) { fv = ov; fi = oi; }
                }
                fi = __shfl_sync(0xffffffffu, fi, 0);    // broadcast winner
                if (lane == k) my_idx = fi;
                if (lane < 8 && hi == fi) {              // advance that list
                    p++; hv = s_wv[lane][p]; hi = s_wi[lane][p];
                }
            }
            // indices + score mean (one parallel load, ordered by flag release)
            float sc = 0.f;
            if (lane < KSEL) {
                g_idx[r * KSEL + lane] = my_idx;
                sc = scores[(size_t)batch * T + my_idx];
            }
#pragma unroll
            for (int o = 16; o; o >>= 1) sc += __shfl_xor_sync(0xffffffffu, sc, o);
            if (lane == 0) {
                out[r] = sc / (float)KSEL;
                st_release(&g_flag[batch], 1);           // orders g_idx stores
            }
        }
    }

    // ---------------- phase 3: gather by the LAST 1280 blocks of the grid --
    if (blk >= GATHER_BASE) {
        int u  = blk - GATHER_BASE;
        int r  = u / KSEL;                 // output row 0..63 (abn first)
        int k  = u % KSEL;
        int gb = (r < HB) ? (HB + r) : (r - HB);

        if (tid == 0) {
            while (ld_acquire(&g_flag[gb]) == 0) __nanosleep(64);
        }
        __syncthreads();
        int idx = __ldcg(&g_idx[r * KSEL + k]);
        const float4* src = (const float4*)(feat + ((size_t)gb * T + idx) * F);
        float4* dst = (float4*)(out + 64 + ((size_t)r * KSEL + k) * F);
        dst[tid] = src[tid];

        // replay-safe reset by the globally last gather block
        if (tid == 0) {
            if (atom_add_acqrel(&g_done, 1) == NGATHER - 1) {
#pragma unroll
                for (int i = 0; i < NB; i++) { g_cnt[i] = 0; g_flag[i] = 0; }
                g_done = 0;
            }
        }
    }
}

extern "C" void kernel_launch(void* const* d_in, const int* in_sizes, int n_in,
                              void* d_out, int out_size) {
    const float* feat   = (const float*)d_in[0];
    const float* scores = (const float*)d_in[1];
    const float* mabn   = (const float*)d_in[2];
    const float* mnor   = (const float*)d_in[3];
    float* out = (float*)d_out;

    fused_kernel<<<GRID, 256>>>(feat, scores, mabn, mnor, out);
}